// round 2
// baseline (speedup 1.0000x reference)
#include <cuda_runtime.h>
#include <cuda_bf16.h>
#include <cstdint>

#define NN   4096
#define IN_D 512
#define OUT_D 128
#define KNET 4
#define ALPHA 0.2f

// Scratch (device globals — no allocation allowed)
__device__ float g_Wh[NN * OUT_D];      // [N, OUT] = h @ W
__device__ float g_Wh1[KNET * NN];      // [K, N]   src projections
__device__ float g_Wh2[KNET * NN];      // [K, N]   dst projections

// ---------------------------------------------------------------------------
// Kernel 1: Wh = h @ W   (M=4096, K=512, N=128)
// CTA: 16 rows x 128 cols, 256 threads, h tile in smem, W streamed via L1.
// ---------------------------------------------------------------------------
__global__ void __launch_bounds__(256) wh_gemm_kernel(
    const float* __restrict__ h, const float* __restrict__ W)
{
    __shared__ float hs[16][IN_D];   // 32 KB
    const int t = threadIdx.x;
    const int row0 = blockIdx.x * 16;

    // stage 16 rows of h (16*512 floats = 2048 float4, 8 per thread)
    {
        const float4* src = reinterpret_cast<const float4*>(h + (size_t)row0 * IN_D);
        float4* dst = reinterpret_cast<float4*>(&hs[0][0]);
        #pragma unroll
        for (int i = 0; i < 8; i++) dst[t + i * 256] = src[t + i * 256];
    }
    __syncthreads();

    const int cg = t & 31;       // 32 col groups * 4 cols
    const int rg = t >> 5;       // 8 row groups * 2 rows
    const int c0 = cg * 4;
    const int i0 = rg * 2;

    float acc[2][4] = {};
    const float4* Wp = reinterpret_cast<const float4*>(W + c0);
    #pragma unroll 4
    for (int k = 0; k < IN_D; k++) {
        float4 w = Wp[(size_t)k * (OUT_D / 4)];
        float a0 = hs[i0][k];
        float a1 = hs[i0 + 1][k];
        acc[0][0] = fmaf(a0, w.x, acc[0][0]);
        acc[0][1] = fmaf(a0, w.y, acc[0][1]);
        acc[0][2] = fmaf(a0, w.z, acc[0][2]);
        acc[0][3] = fmaf(a0, w.w, acc[0][3]);
        acc[1][0] = fmaf(a1, w.x, acc[1][0]);
        acc[1][1] = fmaf(a1, w.y, acc[1][1]);
        acc[1][2] = fmaf(a1, w.z, acc[1][2]);
        acc[1][3] = fmaf(a1, w.w, acc[1][3]);
    }

    #pragma unroll
    for (int r = 0; r < 2; r++) {
        float4 o = make_float4(acc[r][0], acc[r][1], acc[r][2], acc[r][3]);
        *reinterpret_cast<float4*>(&g_Wh[(size_t)(row0 + i0 + r) * OUT_D + c0]) = o;
    }
}

// ---------------------------------------------------------------------------
// Kernel 2: Wh1[k,n] = Wh[n,:] . a[k*256 : +128]
//           Wh2[k,n] = Wh[n,:] . a[k*256+128 : +256]
// One block of 64 threads per n; warp computes 4 of the 8 dots.
// ---------------------------------------------------------------------------
__global__ void __launch_bounds__(64) attn_proj_kernel(const float* __restrict__ a)
{
    __shared__ float whs[OUT_D];
    const int n = blockIdx.x;
    const int t = threadIdx.x;
    whs[t]      = g_Wh[(size_t)n * OUT_D + t];
    whs[t + 64] = g_Wh[(size_t)n * OUT_D + t + 64];
    __syncthreads();

    const int warp = t >> 5;
    const int lane = t & 31;
    #pragma unroll
    for (int c = warp * 4; c < warp * 4 + 4; c++) {
        const int k = c >> 1;
        const int d = c & 1;
        const float* av = a + k * 256 + d * 128;
        float p = whs[lane] * av[lane]
                + whs[lane + 32] * av[lane + 32]
                + whs[lane + 64] * av[lane + 64]
                + whs[lane + 96] * av[lane + 96];
        #pragma unroll
        for (int off = 16; off; off >>= 1)
            p += __shfl_xor_sync(0xffffffffu, p, off);
        if (lane == 0) {
            if (d == 0) g_Wh1[k * NN + n] = p;
            else        g_Wh2[k * NN + n] = p;
        }
    }
}

// ---------------------------------------------------------------------------
// Kernel 3: fused  logits -> mask -> weighted sum -> exp -> (num, den) -> out
//
// Per CTA: BM=16 attention rows, stream m in BK=64 chunks.
//   Phase A (per chunk): E[i][j] = exp( sum_k wts[k]*mask*lrelu(Wh1[k,n]+Wh2[k,m]) )
//   Phase B (per chunk): acc[i][c] += E[i][j] * Wh[m_j][c]   (ti=4 x tc=4 / thread)
// Softmax denominator accumulated alongside; no max subtraction needed:
// logits are a convex combination of lrelu terms bounded by |Wh1|+|Wh2|.
// Masked-out entries contribute exp(0)=1, matching the reference (mask->0
// BEFORE the row softmax).
// ---------------------------------------------------------------------------
__global__ void __launch_bounds__(128, 2) attn_fused_kernel(
    const int* __restrict__ adjs,
    const float* __restrict__ nw,
    float* __restrict__ out)
{
    __shared__ float Wh_s[64 * OUT_D];   // 32 KB: Wh chunk [64 m][128 c]
    __shared__ float E_s[16 * 64];       // 4 KB:  exp(logits) [16 i][64 j]
    __shared__ float denom_s[16];

    const int t  = threadIdx.x;
    const int n0 = blockIdx.x * 16;

    if (t < 16) denom_s[t] = 0.0f;

    // network weights: softmax over nw[0..3] (redundant per thread, trivial)
    float wts[KNET];
    {
        float v0 = nw[0], v1 = nw[1], v2 = nw[2], v3 = nw[3];
        float mx = fmaxf(fmaxf(v0, v1), fmaxf(v2, v3));
        float e0 = __expf(v0 - mx), e1 = __expf(v1 - mx);
        float e2 = __expf(v2 - mx), e3 = __expf(v3 - mx);
        float inv = 1.0f / (e0 + e1 + e2 + e3);
        wts[0] = e0 * inv; wts[1] = e1 * inv; wts[2] = e2 * inv; wts[3] = e3 * inv;
    }

    // logit-phase mapping: 16 rows x 64 j -> 8 elems/thread
    const int li = t >> 3;          // row 0..15
    const int lj = (t & 7) * 8;     // j base (8 consecutive)
    float w1k[KNET];
    #pragma unroll
    for (int k = 0; k < KNET; k++) w1k[k] = g_Wh1[k * NN + n0 + li];

    // per-k adjacency row pointers, advanced by 64 per chunk
    const int* aptr[KNET];
    #pragma unroll
    for (int k = 0; k < KNET; k++)
        aptr[k] = adjs + (size_t)k * NN * NN + (size_t)(n0 + li) * NN + lj;

    // matmul-phase mapping: 4 rowgroups x 4 rows, 32 colgroups x 4 cols
    const int cg = t & 31;
    const int rg = t >> 5;
    const int c0 = cg * 4;
    const int i0 = rg * 4;

    float acc[4][4] = {};
    float denom_local = 0.0f;

    for (int chunk = 0; chunk < NN / 64; chunk++) {
        const int m0 = chunk * 64;
        __syncthreads();   // prev matmul done reading E_s / Wh_s

        // --- stage Wh chunk: 64*128 floats = 2048 float4, 16 per thread ---
        {
            const float4* src = reinterpret_cast<const float4*>(g_Wh + (size_t)m0 * OUT_D);
            float4* dst = reinterpret_cast<float4*>(Wh_s);
            #pragma unroll
            for (int i = 0; i < 16; i++) dst[t + i * 128] = src[t + i * 128];
        }

        // --- logits + exp ---
        float sv[8] = {0.f,0.f,0.f,0.f,0.f,0.f,0.f,0.f};
        #pragma unroll
        for (int k = 0; k < KNET; k++) {
            int4 A0 = *reinterpret_cast<const int4*>(aptr[k]);
            int4 A1 = *reinterpret_cast<const int4*>(aptr[k] + 4);
            aptr[k] += 64;
            const float* wp = g_Wh2 + k * NN + m0 + lj;
            float4 B0 = *reinterpret_cast<const float4*>(wp);
            float4 B1 = *reinterpret_cast<const float4*>(wp + 4);
            const float b  = w1k[k];
            const float wk = wts[k];
            float v;
            v = b + B0.x; v = v > 0.f ? v : ALPHA * v; if (A0.x > 0) sv[0] = fmaf(wk, v, sv[0]);
            v = b + B0.y; v = v > 0.f ? v : ALPHA * v; if (A0.y > 0) sv[1] = fmaf(wk, v, sv[1]);
            v = b + B0.z; v = v > 0.f ? v : ALPHA * v; if (A0.z > 0) sv[2] = fmaf(wk, v, sv[2]);
            v = b + B0.w; v = v > 0.f ? v : ALPHA * v; if (A0.w > 0) sv[3] = fmaf(wk, v, sv[3]);
            v = b + B1.x; v = v > 0.f ? v : ALPHA * v; if (A1.x > 0) sv[4] = fmaf(wk, v, sv[4]);
            v = b + B1.y; v = v > 0.f ? v : ALPHA * v; if (A1.y > 0) sv[5] = fmaf(wk, v, sv[5]);
            v = b + B1.z; v = v > 0.f ? v : ALPHA * v; if (A1.z > 0) sv[6] = fmaf(wk, v, sv[6]);
            v = b + B1.w; v = v > 0.f ? v : ALPHA * v; if (A1.w > 0) sv[7] = fmaf(wk, v, sv[7]);
        }
        float es[8];
        #pragma unroll
        for (int q = 0; q < 8; q++) { es[q] = __expf(sv[q]); denom_local += es[q]; }
        *reinterpret_cast<float4*>(&E_s[li * 64 + lj])     = make_float4(es[0], es[1], es[2], es[3]);
        *reinterpret_cast<float4*>(&E_s[li * 64 + lj + 4]) = make_float4(es[4], es[5], es[6], es[7]);

        __syncthreads();   // E_s / Wh_s ready

        // --- matmul: acc[4][4] += E[i0..+3][j] * Wh_s[j][c0..+3] ---
        #pragma unroll 8
        for (int j = 0; j < 64; j++) {
            float4 w = *reinterpret_cast<const float4*>(&Wh_s[j * OUT_D + c0]);
            float e0 = E_s[(i0 + 0) * 64 + j];
            float e1 = E_s[(i0 + 1) * 64 + j];
            float e2 = E_s[(i0 + 2) * 64 + j];
            float e3 = E_s[(i0 + 3) * 64 + j];
            acc[0][0] = fmaf(e0, w.x, acc[0][0]);
            acc[0][1] = fmaf(e0, w.y, acc[0][1]);
            acc[0][2] = fmaf(e0, w.z, acc[0][2]);
            acc[0][3] = fmaf(e0, w.w, acc[0][3]);
            acc[1][0] = fmaf(e1, w.x, acc[1][0]);
            acc[1][1] = fmaf(e1, w.y, acc[1][1]);
            acc[1][2] = fmaf(e1, w.z, acc[1][2]);
            acc[1][3] = fmaf(e1, w.w, acc[1][3]);
            acc[2][0] = fmaf(e2, w.x, acc[2][0]);
            acc[2][1] = fmaf(e2, w.y, acc[2][1]);
            acc[2][2] = fmaf(e2, w.z, acc[2][2]);
            acc[2][3] = fmaf(e2, w.w, acc[2][3]);
            acc[3][0] = fmaf(e3, w.x, acc[3][0]);
            acc[3][1] = fmaf(e3, w.y, acc[3][1]);
            acc[3][2] = fmaf(e3, w.z, acc[3][2]);
            acc[3][3] = fmaf(e3, w.w, acc[3][3]);
        }
    }

    // reduce denominators (thread's logit row li is fixed across chunks)
    atomicAdd(&denom_s[li], denom_local);
    __syncthreads();

    // epilogue: scale by 1/denom, apply ELU, store
    #pragma unroll
    for (int r = 0; r < 4; r++) {
        const float inv = 1.0f / denom_s[i0 + r];
        float4 o;
        float x;
        x = acc[r][0] * inv; o.x = x > 0.f ? x : __expf(x) - 1.0f;
        x = acc[r][1] * inv; o.y = x > 0.f ? x : __expf(x) - 1.0f;
        x = acc[r][2] * inv; o.z = x > 0.f ? x : __expf(x) - 1.0f;
        x = acc[r][3] * inv; o.w = x > 0.f ? x : __expf(x) - 1.0f;
        *reinterpret_cast<float4*>(&out[(size_t)(n0 + i0 + r) * OUT_D + c0]) = o;
    }
}

// ---------------------------------------------------------------------------
extern "C" void kernel_launch(void* const* d_in, const int* in_sizes, int n_in,
                              void* d_out, int out_size)
{
    const float* h    = (const float*)d_in[0];   // [4096, 512]
    const int*   adjs = (const int*)  d_in[1];   // [4, 4096, 4096]
    const float* W    = (const float*)d_in[2];   // [512, 128]
    const float* a    = (const float*)d_in[3];   // [1024]
    const float* nw   = (const float*)d_in[4];   // [4]
    float* out = (float*)d_out;                  // [4096, 128]

    wh_gemm_kernel<<<NN / 16, 256>>>(h, W);
    attn_proj_kernel<<<NN, 64>>>(a);
    attn_fused_kernel<<<NN / 16, 128>>>(adjs, nw, out);
}

// round 3
// speedup vs baseline: 1.2974x; 1.2974x over previous
#include <cuda_runtime.h>
#include <cuda_bf16.h>
#include <cstdint>

#define NN   4096
#define IN_D 512
#define OUT_D 128
#define KNET 4
#define ALPHA 0.2f
#define NSPLIT 2           // split-K over m-chunks in the fused kernel
#define CHUNKS (NN / 64)   // 64 chunks of 64 columns

// Scratch (device globals — no allocation allowed)
__device__ float g_Wh[NN * OUT_D];              // [N, OUT] = h @ W
__device__ float g_Wh1[KNET * NN];              // [K, N] src projections
__device__ float g_Wh2[KNET * NN];              // [K, N] dst projections
__device__ float g_part[NSPLIT * NN * OUT_D];   // split partial numerators
__device__ float g_den[NSPLIT * NN];            // split partial denominators

// ---------------------------------------------------------------------------
// Kernel 1: Wh = h @ W   (M=4096, K=512, N=128)
// 16 rows/CTA, 256 threads. W streamed with MLP-8 software prefetch so the
// ~250cyc L2 latency is hidden behind each block's 128 FFMAs.
// ---------------------------------------------------------------------------
__global__ void __launch_bounds__(256) wh_gemm_kernel(
    const float* __restrict__ h, const float* __restrict__ W)
{
    __shared__ float hs[16][IN_D];   // 32 KB
    const int t = threadIdx.x;
    const int row0 = blockIdx.x * 16;

    {
        const float4* src = reinterpret_cast<const float4*>(h + (size_t)row0 * IN_D);
        float4* dst = reinterpret_cast<float4*>(&hs[0][0]);
        #pragma unroll
        for (int i = 0; i < 8; i++) dst[t + i * 256] = src[t + i * 256];
    }
    __syncthreads();

    const int cg = t & 31;       // 32 col groups * 4 cols
    const int rg = t >> 5;       // 8 row groups * 2 rows
    const int i0 = rg * 2;
    const int c0 = cg * 4;

    const float4* Wp = reinterpret_cast<const float4*>(W) + cg;  // W[k][c0..c0+3] = Wp[k*32]

    float4 wb[8];
    #pragma unroll
    for (int i = 0; i < 8; i++) wb[i] = Wp[i * 32];

    float acc[2][4] = {};
    for (int kb = 0; kb < IN_D; kb += 8) {
        float4 wn[8];
        const bool more = (kb + 8 < IN_D);
        #pragma unroll
        for (int i = 0; i < 8; i++)
            if (more) wn[i] = Wp[(kb + 8 + i) * 32];
        #pragma unroll
        for (int i = 0; i < 8; i++) {
            const float a0 = hs[i0][kb + i];
            const float a1 = hs[i0 + 1][kb + i];
            acc[0][0] = fmaf(a0, wb[i].x, acc[0][0]);
            acc[0][1] = fmaf(a0, wb[i].y, acc[0][1]);
            acc[0][2] = fmaf(a0, wb[i].z, acc[0][2]);
            acc[0][3] = fmaf(a0, wb[i].w, acc[0][3]);
            acc[1][0] = fmaf(a1, wb[i].x, acc[1][0]);
            acc[1][1] = fmaf(a1, wb[i].y, acc[1][1]);
            acc[1][2] = fmaf(a1, wb[i].z, acc[1][2]);
            acc[1][3] = fmaf(a1, wb[i].w, acc[1][3]);
        }
        #pragma unroll
        for (int i = 0; i < 8; i++) wb[i] = wn[i];
    }

    #pragma unroll
    for (int r = 0; r < 2; r++) {
        float4 o = make_float4(acc[r][0], acc[r][1], acc[r][2], acc[r][3]);
        *reinterpret_cast<float4*>(&g_Wh[(size_t)(row0 + i0 + r) * OUT_D + c0]) = o;
    }
}

// ---------------------------------------------------------------------------
// Kernel 2: Wh1[k,n] = Wh[n,:] . a[k*256 : +128]
//           Wh2[k,n] = Wh[n,:] . a[k*256+128 : +256]
// ---------------------------------------------------------------------------
__global__ void __launch_bounds__(64) attn_proj_kernel(const float* __restrict__ a)
{
    __shared__ float whs[OUT_D];
    const int n = blockIdx.x;
    const int t = threadIdx.x;
    whs[t]      = g_Wh[(size_t)n * OUT_D + t];
    whs[t + 64] = g_Wh[(size_t)n * OUT_D + t + 64];
    __syncthreads();

    const int warp = t >> 5;
    const int lane = t & 31;
    #pragma unroll
    for (int c = warp * 4; c < warp * 4 + 4; c++) {
        const int k = c >> 1;
        const int d = c & 1;
        const float* av = a + k * 256 + d * 128;
        float p = whs[lane] * av[lane]
                + whs[lane + 32] * av[lane + 32]
                + whs[lane + 64] * av[lane + 64]
                + whs[lane + 96] * av[lane + 96];
        #pragma unroll
        for (int off = 16; off; off >>= 1)
            p += __shfl_xor_sync(0xffffffffu, p, off);
        if (lane == 0) {
            if (d == 0) g_Wh1[k * NN + n] = p;
            else        g_Wh2[k * NN + n] = p;
        }
    }
}

// ---------------------------------------------------------------------------
// Kernel 3: fused logits -> mask -> weighted sum -> exp -> partial (num, den)
// Grid (NN/16, NSPLIT): blockIdx.y selects which half of the m-chunks this
// CTA accumulates (split-K) -> 512 CTAs, ~3.5 CTA/SM for phase overlap.
// Masked entries contribute exp(0)=1, matching the reference.
// ---------------------------------------------------------------------------
__global__ void __launch_bounds__(128, 4) attn_fused_kernel(
    const int* __restrict__ adjs,
    const float* __restrict__ nw)
{
    __shared__ float Wh_s[64 * OUT_D];   // 32 KB
    __shared__ float E_s[16 * 64];       // 4 KB
    __shared__ float denom_s[16];

    const int t  = threadIdx.x;
    const int n0 = blockIdx.x * 16;
    const int s  = blockIdx.y;           // split id
    const int chunk0 = s * (CHUNKS / NSPLIT);
    const int chunk1 = chunk0 + (CHUNKS / NSPLIT);

    if (t < 16) denom_s[t] = 0.0f;

    float wts[KNET];
    {
        float v0 = nw[0], v1 = nw[1], v2 = nw[2], v3 = nw[3];
        float mx = fmaxf(fmaxf(v0, v1), fmaxf(v2, v3));
        float e0 = __expf(v0 - mx), e1 = __expf(v1 - mx);
        float e2 = __expf(v2 - mx), e3 = __expf(v3 - mx);
        float inv = 1.0f / (e0 + e1 + e2 + e3);
        wts[0] = e0 * inv; wts[1] = e1 * inv; wts[2] = e2 * inv; wts[3] = e3 * inv;
    }

    // logit-phase mapping: 16 rows x 64 j -> 8 elems/thread
    const int li = t >> 3;
    const int lj = (t & 7) * 8;
    float w1k[KNET];
    #pragma unroll
    for (int k = 0; k < KNET; k++) w1k[k] = g_Wh1[k * NN + n0 + li];

    const int* aptr[KNET];
    #pragma unroll
    for (int k = 0; k < KNET; k++)
        aptr[k] = adjs + (size_t)k * NN * NN + (size_t)(n0 + li) * NN + chunk0 * 64 + lj;

    // matmul-phase mapping
    const int cg = t & 31;
    const int rg = t >> 5;
    const int c0 = cg * 4;
    const int i0 = rg * 4;

    float acc[4][4] = {};
    float denom_local = 0.0f;

    for (int chunk = chunk0; chunk < chunk1; chunk++) {
        const int m0 = chunk * 64;
        __syncthreads();

        // stage Wh chunk
        {
            const float4* src = reinterpret_cast<const float4*>(g_Wh + (size_t)m0 * OUT_D);
            float4* dst = reinterpret_cast<float4*>(Wh_s);
            #pragma unroll
            for (int i = 0; i < 16; i++) dst[t + i * 128] = src[t + i * 128];
        }

        // logits + exp
        float sv[8] = {0.f,0.f,0.f,0.f,0.f,0.f,0.f,0.f};
        #pragma unroll
        for (int k = 0; k < KNET; k++) {
            int4 A0 = *reinterpret_cast<const int4*>(aptr[k]);
            int4 A1 = *reinterpret_cast<const int4*>(aptr[k] + 4);
            aptr[k] += 64;
            const float* wp = g_Wh2 + k * NN + m0 + lj;
            float4 B0 = *reinterpret_cast<const float4*>(wp);
            float4 B1 = *reinterpret_cast<const float4*>(wp + 4);
            const float b  = w1k[k];
            const float wk = wts[k];
            float v;
            v = b + B0.x; v = v > 0.f ? v : ALPHA * v; if (A0.x > 0) sv[0] = fmaf(wk, v, sv[0]);
            v = b + B0.y; v = v > 0.f ? v : ALPHA * v; if (A0.y > 0) sv[1] = fmaf(wk, v, sv[1]);
            v = b + B0.z; v = v > 0.f ? v : ALPHA * v; if (A0.z > 0) sv[2] = fmaf(wk, v, sv[2]);
            v = b + B0.w; v = v > 0.f ? v : ALPHA * v; if (A0.w > 0) sv[3] = fmaf(wk, v, sv[3]);
            v = b + B1.x; v = v > 0.f ? v : ALPHA * v; if (A1.x > 0) sv[4] = fmaf(wk, v, sv[4]);
            v = b + B1.y; v = v > 0.f ? v : ALPHA * v; if (A1.y > 0) sv[5] = fmaf(wk, v, sv[5]);
            v = b + B1.z; v = v > 0.f ? v : ALPHA * v; if (A1.z > 0) sv[6] = fmaf(wk, v, sv[6]);
            v = b + B1.w; v = v > 0.f ? v : ALPHA * v; if (A1.w > 0) sv[7] = fmaf(wk, v, sv[7]);
        }
        float es[8];
        #pragma unroll
        for (int q = 0; q < 8; q++) { es[q] = __expf(sv[q]); denom_local += es[q]; }
        *reinterpret_cast<float4*>(&E_s[li * 64 + lj])     = make_float4(es[0], es[1], es[2], es[3]);
        *reinterpret_cast<float4*>(&E_s[li * 64 + lj + 4]) = make_float4(es[4], es[5], es[6], es[7]);

        __syncthreads();

        // matmul: acc[4][4] += E[i0..+3][j] * Wh_s[j][c0..+3]
        #pragma unroll 8
        for (int j = 0; j < 64; j++) {
            float4 w = *reinterpret_cast<const float4*>(&Wh_s[j * OUT_D + c0]);
            float e0 = E_s[(i0 + 0) * 64 + j];
            float e1 = E_s[(i0 + 1) * 64 + j];
            float e2 = E_s[(i0 + 2) * 64 + j];
            float e3 = E_s[(i0 + 3) * 64 + j];
            acc[0][0] = fmaf(e0, w.x, acc[0][0]);
            acc[0][1] = fmaf(e0, w.y, acc[0][1]);
            acc[0][2] = fmaf(e0, w.z, acc[0][2]);
            acc[0][3] = fmaf(e0, w.w, acc[0][3]);
            acc[1][0] = fmaf(e1, w.x, acc[1][0]);
            acc[1][1] = fmaf(e1, w.y, acc[1][1]);
            acc[1][2] = fmaf(e1, w.z, acc[1][2]);
            acc[1][3] = fmaf(e1, w.w, acc[1][3]);
            acc[2][0] = fmaf(e2, w.x, acc[2][0]);
            acc[2][1] = fmaf(e2, w.y, acc[2][1]);
            acc[2][2] = fmaf(e2, w.z, acc[2][2]);
            acc[2][3] = fmaf(e2, w.w, acc[2][3]);
            acc[3][0] = fmaf(e3, w.x, acc[3][0]);
            acc[3][1] = fmaf(e3, w.y, acc[3][1]);
            acc[3][2] = fmaf(e3, w.z, acc[3][2]);
            acc[3][3] = fmaf(e3, w.w, acc[3][3]);
        }
    }

    atomicAdd(&denom_s[li], denom_local);
    __syncthreads();

    if (t < 16) g_den[s * NN + n0 + t] = denom_s[t];

    #pragma unroll
    for (int r = 0; r < 4; r++) {
        float4 o = make_float4(acc[r][0], acc[r][1], acc[r][2], acc[r][3]);
        *reinterpret_cast<float4*>(
            &g_part[((size_t)s * NN + n0 + i0 + r) * OUT_D + c0]) = o;
    }
}

// ---------------------------------------------------------------------------
// Kernel 4: combine splits, softmax-normalize, ELU, store
// ---------------------------------------------------------------------------
__global__ void __launch_bounds__(256) finalize_kernel(float* __restrict__ out)
{
    const int idx = blockIdx.x * 256 + threadIdx.x;   // over NN*OUT_D/4 float4s
    const int n = idx >> 5;                            // 32 float4 per row
    const float4 p0 = reinterpret_cast<const float4*>(g_part)[idx];
    const float4 p1 = reinterpret_cast<const float4*>(g_part)[idx + NN * OUT_D / 4];
    const float inv = 1.0f / (g_den[n] + g_den[NN + n]);
    float4 o;
    float x;
    x = (p0.x + p1.x) * inv; o.x = x > 0.f ? x : __expf(x) - 1.0f;
    x = (p0.y + p1.y) * inv; o.y = x > 0.f ? x : __expf(x) - 1.0f;
    x = (p0.z + p1.z) * inv; o.z = x > 0.f ? x : __expf(x) - 1.0f;
    x = (p0.w + p1.w) * inv; o.w = x > 0.f ? x : __expf(x) - 1.0f;
    reinterpret_cast<float4*>(out)[idx] = o;
}

// ---------------------------------------------------------------------------
extern "C" void kernel_launch(void* const* d_in, const int* in_sizes, int n_in,
                              void* d_out, int out_size)
{
    const float* h    = (const float*)d_in[0];   // [4096, 512]
    const int*   adjs = (const int*)  d_in[1];   // [4, 4096, 4096]
    const float* W    = (const float*)d_in[2];   // [512, 128]
    const float* a    = (const float*)d_in[3];   // [1024]
    const float* nw   = (const float*)d_in[4];   // [4]
    float* out = (float*)d_out;                  // [4096, 128]

    wh_gemm_kernel<<<NN / 16, 256>>>(h, W);
    attn_proj_kernel<<<NN, 64>>>(a);
    attn_fused_kernel<<<dim3(NN / 16, NSPLIT), 128>>>(adjs, nw);
    finalize_kernel<<<NN * OUT_D / 4 / 256, 256>>>(out);
}